// round 13
// baseline (speedup 1.0000x reference)
#include <cuda_runtime.h>

// Problem constants
#define NH    5
#define LD    10
#define PROJ  50           // NH*LD
#define C_DIM 256
#define B_DIM 32
#define HW    4096
#define M_ROWS (B_DIM * C_DIM)   // 8192
#define BN_EPS 1e-5f
#define KSPLIT 8
#define KSLICE (HW / KSPLIT)     // 512

// Scratch (device globals: no allocations allowed)
__device__ float g_Pp[3][KSPLIT][M_ROWS * PROJ];  // split-K partials
__device__ float g_P[3][M_ROWS * PROJ];           // reduced projections
// Packed mma fragments (built once per launch, L2-resident):
__device__ uint4 g_Wp[64 * 4 * 7 * 32];           // wfc as mma-A frags
__device__ uint2 g_Vp[1024 * 7 * 32];             // Va  as mma-B frags
__device__ float g_gramp[B_DIM][8][NH * NH];      // partial Gram sums
__device__ float g_attn[B_DIM][NH * NH];          // softmax(S)
__device__ float g_osum[64][M_ROWS];              // per-(nblk,row) sum of out
__device__ float g_osq[64][M_ROWS];               // per-(nblk,row) sum of out^2
__device__ float g_scale[C_DIM];
__device__ float g_shift[C_DIM];

__device__ __forceinline__ unsigned f2tf32(float x) {
    unsigned y;
    asm("cvt.rna.tf32.f32 %0, %1;" : "=r"(y) : "f"(x));
    return y;
}

__device__ __forceinline__ void mma_tf32(float c[4], unsigned a0, unsigned a1,
                                         unsigned a2, unsigned a3,
                                         unsigned b0, unsigned b1) {
    asm volatile(
        "mma.sync.aligned.m16n8k8.row.col.f32.tf32.tf32.f32 "
        "{%0,%1,%2,%3}, {%4,%5,%6,%7}, {%8,%9}, {%0,%1,%2,%3};\n"
        : "+f"(c[0]), "+f"(c[1]), "+f"(c[2]), "+f"(c[3])
        : "r"(a0), "r"(a1), "r"(a2), "r"(a3), "r"(b0), "r"(b1));
}

__device__ __forceinline__ void cp_async16(unsigned smem_dst, const void* gsrc) {
    asm volatile("cp.async.cg.shared.global [%0], [%1], 16;\n"
                 :: "r"(smem_dst), "l"(gsrc));
}
__device__ __forceinline__ void cp_commit() {
    asm volatile("cp.async.commit_group;\n");
}
__device__ __forceinline__ void cp_wait0() {
    asm volatile("cp.async.wait_group 0;\n");
}

// ---------------------------------------------------------------------------
// K1: projection GEMMs (R7 kernel, split-K x8).
// SWAPPED mma roles: mma-A = W (n50 as M), mma-B = data rows (as N).
// ---------------------------------------------------------------------------
__global__ __launch_bounds__(256) void k_proj_tc(
    const float* __restrict__ q, const float* __restrict__ k,
    const float* __restrict__ v,
    const float* __restrict__ wq, const float* __restrict__ wk,
    const float* __restrict__ wv)
{
    const int z = blockIdx.z;
    const float* __restrict__ A = (z == 0) ? q : (z == 1) ? k : v;
    const float* __restrict__ W = (z == 0) ? wq : (z == 1) ? wk : wv;
    const int slice = blockIdx.y;
    float* __restrict__ P = g_Pp[z][slice];
    const int kbase = slice * KSLICE;

    __shared__ unsigned As[2][128][32];
    __shared__ unsigned Wsm[64][36];

    const int tid  = threadIdx.x;
    const int warp = tid >> 5;
    const int lane = tid & 31;
    const int g = lane >> 2;
    const int t = lane & 3;
    const int wrow = (warp & 3) * 32;
    const int wcol = (warp >> 2) * 32;
    const int m0 = blockIdx.x * 128;

    const unsigned as_base = (unsigned)__cvta_generic_to_shared(&As[0][0][0]);

    for (int i = tid; i < 64 * 36; i += 256) (&Wsm[0][0])[i] = 0u;
    __syncthreads();

    float acc[2][4][4];
#pragma unroll
    for (int mi = 0; mi < 2; mi++)
#pragma unroll
        for (int ni = 0; ni < 4; ni++)
#pragma unroll
            for (int r = 0; r < 4; r++) acc[mi][ni][r] = 0.f;

    const int wl_n  = tid & 63;
    const int wl_k0 = (tid >> 6) * 8;

    auto issue_A = [&](int buf, int k0) {
#pragma unroll
        for (int j = 0; j < 4; j++) {
            int i   = tid + j * 256;
            int row = i >> 3;
            int c4  = (i & 7) * 4;
            int sc  = c4 ^ (4 * (row & 7));
            unsigned dst = as_base + ((buf * 128 + row) * 32 + sc) * 4;
            cp_async16(dst, &A[(size_t)(m0 + row) * HW + k0 + c4]);
        }
        cp_commit();
    };

    issue_A(0, kbase);
    if (wl_n < PROJ) {
#pragma unroll
        for (int j = 0; j < 8; j++)
            Wsm[wl_n][wl_k0 + j] = f2tf32(W[(kbase + wl_k0 + j) * PROJ + wl_n]);
    }
    cp_wait0();
    __syncthreads();

    const int NT = KSLICE / 32;   // 16 tiles
    for (int kt = 0; kt < NT; kt++) {
        const int buf = kt & 1;
        const bool haveNext = (kt + 1 < NT);
        float wreg[8];
        if (haveNext) {
            const int k0n = kbase + (kt + 1) * 32;
            issue_A(buf ^ 1, k0n);
            if (wl_n < PROJ) {
#pragma unroll
                for (int j = 0; j < 8; j++)
                    wreg[j] = W[(k0n + wl_k0 + j) * PROJ + wl_n];
            }
        }

#pragma unroll
        for (int ks = 0; ks < 4; ks++) {
            const int kb = ks * 8;
            unsigned a[2][4];
#pragma unroll
            for (int mi = 0; mi < 2; mi++) {
                int n = wcol + mi * 16 + g;
                a[mi][0] = Wsm[n][kb + t];
                a[mi][1] = Wsm[n + 8][kb + t];
                a[mi][2] = Wsm[n][kb + t + 4];
                a[mi][3] = Wsm[n + 8][kb + t + 4];
            }
#pragma unroll
            for (int ni = 0; ni < 4; ni++) {
                int row = wrow + ni * 8 + g;
                unsigned b0 = As[buf][row][(kb + t) ^ (4 * (row & 7))];
                unsigned b1 = As[buf][row][(kb + t + 4) ^ (4 * (row & 7))];
                mma_tf32(acc[0][ni], a[0][0], a[0][1], a[0][2], a[0][3], b0, b1);
                mma_tf32(acc[1][ni], a[1][0], a[1][1], a[1][2], a[1][3], b0, b1);
            }
        }

        if (haveNext) {
            cp_wait0();
            __syncthreads();
            if (wl_n < PROJ) {
#pragma unroll
                for (int j = 0; j < 8; j++)
                    Wsm[wl_n][wl_k0 + j] = f2tf32(wreg[j]);
            }
            __syncthreads();
        }
    }

#pragma unroll
    for (int mi = 0; mi < 2; mi++) {
#pragma unroll
        for (int ni = 0; ni < 4; ni++) {
            int col0 = wcol + mi * 16 + g;
            int col2 = col0 + 8;
            int prow = m0 + wrow + ni * 8 + 2 * t;
            if (col0 < PROJ) {
                P[prow * PROJ + col0]       = acc[mi][ni][0];
                P[(prow + 1) * PROJ + col0] = acc[mi][ni][1];
            }
            if (col2 < PROJ) {
                P[prow * PROJ + col2]       = acc[mi][ni][2];
                P[(prow + 1) * PROJ + col2] = acc[mi][ni][3];
            }
        }
    }
}

// ---------------------------------------------------------------------------
// K1b: reduce split-K partials (8-way).
// ---------------------------------------------------------------------------
__global__ __launch_bounds__(256) void k_reduceP()
{
    const int i = blockIdx.x * 256 + threadIdx.x;
    const int per_z = (M_ROWS * PROJ) / 4;
    const int z = i / per_z;
    const int r = i - z * per_z;
    const float4* __restrict__ p = (const float4*)g_Pp;
    float4 o = make_float4(0.f, 0.f, 0.f, 0.f);
#pragma unroll
    for (int j = 0; j < KSPLIT; j++) {
        float4 a = p[(size_t)(z * KSPLIT + j) * per_z + r];
        o.x += a.x; o.y += a.y; o.z += a.z; o.w += a.w;
    }
    ((float4*)g_P)[i] = o;
}

// ---------------------------------------------------------------------------
// K1c: pack wfc into mma-A fragment order (once; 917 KB, L2-resident).
// ---------------------------------------------------------------------------
__global__ __launch_bounds__(256) void k_packW(const float* __restrict__ wfc)
{
    const int idx = blockIdx.x * 256 + threadIdx.x;   // 0 .. 229375
    const int kk = idx >> 12;
    const int n  = idx & 4095;
    float val = (kk < PROJ) ? wfc[kk * HW + n] : 0.f;
    const int nblk = n >> 6, n6 = n & 63;
    const int N16 = n6 >> 4, hi = (n6 >> 3) & 1, gg = n6 & 7;
    const int K8 = kk >> 3, tt = kk & 3, hf = (kk >> 2) & 1;
    ((unsigned*)g_Wp)[(((nblk * 4 + N16) * 7 + K8) * 32 + gg * 4 + tt) * 4
                      + hi + 2 * hf] = f2tf32(val);
}

// ---------------------------------------------------------------------------
// K2a: Gram partials. grid (32 b, 8 cslice); 256 thr = 32 channels x 8 workers.
// Worker w handles l in {w, w+8 (if <10)}. Fixed-order reductions.
// ---------------------------------------------------------------------------
__global__ __launch_bounds__(256) void k_gram()
{
    const int b  = blockIdx.x;
    const int cs = blockIdx.y;
    const int tid = threadIdx.x;
    const int cl = tid >> 3;          // 0..31 channel-local
    const int w  = tid & 7;           // worker
    const int row = b * C_DIM + cs * 32 + cl;

    const float* __restrict__ pq = &g_P[0][row * PROJ];
    const float* __restrict__ pk = &g_P[1][row * PROJ];

    float qv[NH][2], kv[NH][2];
    const bool has2 = (w + 8 < LD);
#pragma unroll
    for (int i = 0; i < NH; i++) {
        qv[i][0] = __ldg(&pq[i * LD + w]);
        kv[i][0] = __ldg(&pk[i * LD + w]);
        qv[i][1] = has2 ? __ldg(&pq[i * LD + w + 8]) : 0.f;
        kv[i][1] = has2 ? __ldg(&pk[i * LD + w + 8]) : 0.f;
    }

    __shared__ float sG[32][26];

#pragma unroll
    for (int i = 0; i < NH; i++) {
#pragma unroll
        for (int j = 0; j < NH; j++) {
            float s = qv[i][0] * kv[j][0] + qv[i][1] * kv[j][1];
            // reduce over 8 workers (contiguous lanes)
            s += __shfl_xor_sync(0xffffffffu, s, 1);
            s += __shfl_xor_sync(0xffffffffu, s, 2);
            s += __shfl_xor_sync(0xffffffffu, s, 4);
            if (w == 0) sG[cl][i * NH + j] = s;
        }
    }
    __syncthreads();

    if (tid < NH * NH) {  // reduce 32 channels, fixed order
        float a = 0.f;
#pragma unroll
        for (int cc = 0; cc < 32; cc++) a += sG[cc][tid];
        g_gramp[b][cs][tid] = a;
    }
}

// ---------------------------------------------------------------------------
// K2b: softmax. 1 block, 32 threads (one per batch).
// ---------------------------------------------------------------------------
__global__ __launch_bounds__(32) void k_soft()
{
    const int b = threadIdx.x;
    const float inv_scale = rsqrtf((float)(C_DIM * LD));
    float s[NH * NH];
#pragma unroll
    for (int tt = 0; tt < NH * NH; tt++) {
        float a = 0.f;
#pragma unroll
        for (int cs = 0; cs < 8; cs++) a += g_gramp[b][cs][tt];
        s[tt] = a * inv_scale;
    }
#pragma unroll
    for (int i = 0; i < NH; i++) {
        float mx = -1e30f;
#pragma unroll
        for (int j = 0; j < NH; j++) mx = fmaxf(mx, s[i * NH + j]);
        float sum = 0.f;
#pragma unroll
        for (int j = 0; j < NH; j++) {
            s[i * NH + j] = expf(s[i * NH + j] - mx);
            sum += s[i * NH + j];
        }
        float inv = 1.f / sum;
#pragma unroll
        for (int j = 0; j < NH; j++) g_attn[b][i * NH + j] = s[i * NH + j] * inv;
    }
}

// ---------------------------------------------------------------------------
// K2c: Va = Pv + attn @ Pv (per channel), written in packed mma-B frag order.
// grid 32 blocks x 256 thr (thread = channel).
// ---------------------------------------------------------------------------
__global__ __launch_bounds__(256) void k_vawrite()
{
    const int b = blockIdx.x;
    const int c = threadIdx.x;
    const int row = b * C_DIM + c;
    const float* __restrict__ pv = &g_P[2][row * PROJ];

    __shared__ float sA[NH * NH];
    if (c < NH * NH) sA[c] = g_attn[b][c];
    __syncthreads();

    const int R8i = row >> 3, gg = row & 7;
    unsigned* __restrict__ vp = (unsigned*)g_Vp;
#pragma unroll
    for (int n = 0; n < NH; n++)
#pragma unroll
        for (int l = 0; l < LD; l++) {
            float a = pv[n * LD + l];
#pragma unroll
            for (int j = 0; j < NH; j++)
                a = fmaf(sA[n * NH + j], pv[j * LD + l], a);
            const int kk = n * LD + l;
            const int K8 = kk >> 3, tt = kk & 3, hf = (kk >> 2) & 1;
            vp[((R8i * 7 + K8) * 32 + gg * 4 + tt) * 2 + hf] = f2tf32(a);
        }
#pragma unroll
    for (int kk = PROJ; kk < 56; kk++) {
        const int K8 = kk >> 3, tt = kk & 3, hf = (kk >> 2) & 1;
        vp[((R8i * 7 + K8) * 32 + gg * 4 + tt) * 2 + hf] = 0u;
    }
}

// ---------------------------------------------------------------------------
// Shared lean GEMM mainloop + Acc staging (fragments from packed globals).
// ---------------------------------------------------------------------------
#define OUT_MAINLOOP_AND_STAGE(ACC)                                            \
    const uint4* __restrict__ Wp =                                             \
        g_Wp + (size_t)(blockIdx.x * 4 + (warp >> 2) * 2) * 7 * 32;            \
    const uint2* __restrict__ Vp =                                             \
        g_Vp + (size_t)((m0 >> 3) + (warp & 3) * 4) * 7 * 32;                  \
    _Pragma("unroll")                                                          \
    for (int ks = 0; ks < 7; ks++) {                                           \
        uint4 av0 = __ldg(&Wp[ks * 32 + lane]);                                \
        uint4 av1 = __ldg(&Wp[(7 + ks) * 32 + lane]);                          \
        _Pragma("unroll")                                                      \
        for (int ni = 0; ni < 4; ni++) {                                       \
            uint2 bv = __ldg(&Vp[(ni * 7 + ks) * 32 + lane]);                  \
            mma_tf32(ACC[0][ni], av0.x, av0.y, av0.z, av0.w, bv.x, bv.y);      \
            mma_tf32(ACC[1][ni], av1.x, av1.y, av1.z, av1.w, bv.x, bv.y);      \
        }                                                                      \
    }                                                                          \
    _Pragma("unroll")                                                          \
    for (int mi = 0; mi < 2; mi++) {                                           \
        _Pragma("unroll")                                                      \
        for (int ni = 0; ni < 4; ni++) {                                       \
            int row = wrow + ni * 8 + 2 * t;                                   \
            int col = wcol + mi * 16 + g;                                      \
            Acc[row][col]         = ACC[mi][ni][0];                            \
            Acc[row + 1][col]     = ACC[mi][ni][1];                            \
            Acc[row][col + 8]     = ACC[mi][ni][2];                            \
            Acc[row + 1][col + 8] = ACC[mi][ni][3];                            \
        }                                                                      \
    }                                                                          \
    __syncthreads();

// ---------------------------------------------------------------------------
// K3a: stats pass. o = v + Va@wfc computed, per-row sum/sumsq written,
// out NOT written.
// ---------------------------------------------------------------------------
__global__ __launch_bounds__(256) void k_out_stats(const float* __restrict__ v)
{
    __shared__ float Acc[128][68];

    const int tid  = threadIdx.x;
    const int warp = tid >> 5;
    const int lane = tid & 31;
    const int g = lane >> 2;
    const int t = lane & 3;
    const int wrow = (warp & 3) * 32;
    const int wcol = (warp >> 2) * 32;
    const int n0 = blockIdx.x * 64;
    const int m0 = blockIdx.y * 128;

    float acc[2][4][4];
#pragma unroll
    for (int mi = 0; mi < 2; mi++)
#pragma unroll
        for (int ni = 0; ni < 4; ni++)
#pragma unroll
            for (int r = 0; r < 4; r++) acc[mi][ni][r] = 0.f;

    OUT_MAINLOOP_AND_STAGE(acc)

#pragma unroll
    for (int it = 0; it < 8; it++) {
        int f   = tid + it * 256;
        int row = f >> 4;
        int c4  = (f & 15) * 4;
        float4 a = *(float4*)&Acc[row][c4];
        size_t gi = (size_t)(m0 + row) * HW + n0 + c4;
        float4 vv = *(const float4*)&v[gi];
        float ox = vv.x + a.x, oy = vv.y + a.y;
        float oz = vv.z + a.z, ow = vv.w + a.w;
        float s  = (ox + oy) + (oz + ow);
        float qq = (ox * ox + oy * oy) + (oz * oz + ow * ow);
#pragma unroll
        for (int msk = 1; msk <= 8; msk <<= 1) {
            s  += __shfl_xor_sync(0xffffffffu, s, msk);
            qq += __shfl_xor_sync(0xffffffffu, qq, msk);
        }
        if ((lane & 15) == 0) {
            g_osum[blockIdx.x][m0 + row] = s;
            g_osq[blockIdx.x][m0 + row]  = qq;
        }
    }
}

// ---------------------------------------------------------------------------
// K4: combine partials -> per-channel scale/shift.
// ---------------------------------------------------------------------------
__global__ __launch_bounds__(256) void k_bnfinal(
    const float* __restrict__ gamma, const float* __restrict__ beta)
{
    const int c = blockIdx.x;
    const int tid = threadIdx.x;
    float s = 0.f, s2 = 0.f;
    for (int i = tid; i < B_DIM * 64; i += 256) {
        int b  = i >> 6;
        int nb = i & 63;
        int row = b * C_DIM + c;
        s  += g_osum[nb][row];
        s2 += g_osq[nb][row];
    }
    __shared__ float rs[256], rs2[256];
    rs[tid] = s; rs2[tid] = s2;
    __syncthreads();
    for (int off = 128; off > 0; off >>= 1) {
        if (tid < off) { rs[tid] += rs[tid + off]; rs2[tid] += rs2[tid + off]; }
        __syncthreads();
    }
    if (tid == 0) {
        const float inv_n = 1.f / (float)(B_DIM * HW);
        float mean = rs[0] * inv_n;
        float var  = rs2[0] * inv_n - mean * mean;
        float sc = gamma[c] * rsqrtf(var + BN_EPS);
        g_scale[c] = sc;
        g_shift[c] = beta[c] - mean * sc;
    }
}

// ---------------------------------------------------------------------------
// K3b: apply pass. Recomputes the identical GEMM (bit-identical acc),
// writes out = (v + acc)*scale[c] + shift[c]. Single out write, no re-read.
// ---------------------------------------------------------------------------
__global__ __launch_bounds__(256) void k_apply_gemm(
    const float* __restrict__ v, float* __restrict__ out)
{
    __shared__ float Acc[128][68];

    const int tid  = threadIdx.x;
    const int warp = tid >> 5;
    const int lane = tid & 31;
    const int g = lane >> 2;
    const int t = lane & 3;
    const int wrow = (warp & 3) * 32;
    const int wcol = (warp >> 2) * 32;
    const int n0 = blockIdx.x * 64;
    const int m0 = blockIdx.y * 128;

    float acc[2][4][4];
#pragma unroll
    for (int mi = 0; mi < 2; mi++)
#pragma unroll
        for (int ni = 0; ni < 4; ni++)
#pragma unroll
            for (int r = 0; r < 4; r++) acc[mi][ni][r] = 0.f;

    OUT_MAINLOOP_AND_STAGE(acc)

#pragma unroll
    for (int it = 0; it < 8; it++) {
        int f   = tid + it * 256;
        int row = f >> 4;
        int c4  = (f & 15) * 4;
        int ch  = (m0 + row) & (C_DIM - 1);
        float sc = g_scale[ch], sh = g_shift[ch];
        float4 a = *(float4*)&Acc[row][c4];
        size_t gi = (size_t)(m0 + row) * HW + n0 + c4;
        float4 vv = *(const float4*)&v[gi];
        float4 o;
        o.x = fmaf(vv.x + a.x, sc, sh);
        o.y = fmaf(vv.y + a.y, sc, sh);
        o.z = fmaf(vv.z + a.z, sc, sh);
        o.w = fmaf(vv.w + a.w, sc, sh);
        *(float4*)&out[gi] = o;
    }
}

// ---------------------------------------------------------------------------
extern "C" void kernel_launch(void* const* d_in, const int* in_sizes, int n_in,
                              void* d_out, int out_size)
{
    (void)in_sizes; (void)n_in; (void)out_size;
    const float* q     = (const float*)d_in[0];
    const float* k     = (const float*)d_in[1];
    const float* v     = (const float*)d_in[2];
    const float* wq    = (const float*)d_in[3];
    const float* wk    = (const float*)d_in[4];
    const float* wv    = (const float*)d_in[5];
    const float* wfc   = (const float*)d_in[6];
    const float* gamma = (const float*)d_in[7];
    const float* beta  = (const float*)d_in[8];
    float* out = (float*)d_out;

    k_proj_tc<<<dim3(M_ROWS / 128, KSPLIT, 3), 256>>>(q, k, v, wq, wk, wv);
    k_packW<<<(4096 * 56) / 256, 256>>>(wfc);
    k_reduceP<<<(3 * M_ROWS * PROJ / 4) / 256, 256>>>();
    k_gram<<<dim3(B_DIM, 8), 256>>>();
    k_soft<<<1, 32>>>();
    k_vawrite<<<B_DIM, 256>>>();
    k_out_stats<<<dim3(HW / 64, M_ROWS / 128), 256>>>(v);
    k_bnfinal<<<C_DIM, 256>>>(gamma, beta);
    k_apply_gemm<<<dim3(HW / 64, M_ROWS / 128), 256>>>(v, out);
}

// round 16
// speedup vs baseline: 1.0157x; 1.0157x over previous
#include <cuda_runtime.h>

// Problem constants
#define NH    5
#define LD    10
#define PROJ  50           // NH*LD
#define C_DIM 256
#define B_DIM 32
#define HW    4096
#define M_ROWS (B_DIM * C_DIM)   // 8192
#define BN_EPS 1e-5f
#define KSPLIT 4
#define KSLICE (HW / KSPLIT)     // 1024

// Scratch (device globals: no allocations allowed)
__device__ float g_Pp[3][KSPLIT][M_ROWS * PROJ];  // split-K partials
__device__ float g_P[3][M_ROWS * PROJ];           // reduced projections
// Packed mma fragments (built once per launch, L2-resident):
__device__ uint4 g_Wp[64 * 4 * 7 * 32];           // wfc as mma-A frags
__device__ uint2 g_Vp[1024 * 7 * 32];             // Va  as mma-B frags
__device__ float g_gramp[B_DIM][8][NH * NH];      // partial Gram sums
__device__ float g_attn[B_DIM][NH * NH];          // softmax(S)
__device__ float g_osum[64][M_ROWS];              // per-(nblk,row) sum of out
__device__ float g_osq[64][M_ROWS];               // per-(nblk,row) sum of out^2
__device__ float g_scale[C_DIM];
__device__ float g_shift[C_DIM];

__device__ __forceinline__ unsigned f2tf32(float x) {
    unsigned y;
    asm("cvt.rna.tf32.f32 %0, %1;" : "=r"(y) : "f"(x));
    return y;
}

__device__ __forceinline__ void mma_tf32(float c[4], unsigned a0, unsigned a1,
                                         unsigned a2, unsigned a3,
                                         unsigned b0, unsigned b1) {
    asm volatile(
        "mma.sync.aligned.m16n8k8.row.col.f32.tf32.tf32.f32 "
        "{%0,%1,%2,%3}, {%4,%5,%6,%7}, {%8,%9}, {%0,%1,%2,%3};\n"
        : "+f"(c[0]), "+f"(c[1]), "+f"(c[2]), "+f"(c[3])
        : "r"(a0), "r"(a1), "r"(a2), "r"(a3), "r"(b0), "r"(b1));
}

__device__ __forceinline__ void cp_async16(unsigned smem_dst, const void* gsrc) {
    asm volatile("cp.async.cg.shared.global [%0], [%1], 16;\n"
                 :: "r"(smem_dst), "l"(gsrc));
}
__device__ __forceinline__ void cp_commit() {
    asm volatile("cp.async.commit_group;\n");
}
__device__ __forceinline__ void cp_wait0() {
    asm volatile("cp.async.wait_group 0;\n");
}

// ---------------------------------------------------------------------------
// K1: projection GEMMs (R7/R12 kernel: static smem, W single-buffer + reg
// prefetch, cp.async A double-buffer, split-K x4).
// SWAPPED mma roles: mma-A = W (n50 as M), mma-B = data rows (as N).
// ---------------------------------------------------------------------------
__global__ __launch_bounds__(256) void k_proj_tc(
    const float* __restrict__ q, const float* __restrict__ k,
    const float* __restrict__ v,
    const float* __restrict__ wq, const float* __restrict__ wk,
    const float* __restrict__ wv)
{
    const int z = blockIdx.z;
    const float* __restrict__ A = (z == 0) ? q : (z == 1) ? k : v;
    const float* __restrict__ W = (z == 0) ? wq : (z == 1) ? wk : wv;
    const int slice = blockIdx.y;
    float* __restrict__ P = g_Pp[z][slice];
    const int kbase = slice * KSLICE;

    __shared__ unsigned As[2][128][32];
    __shared__ unsigned Wsm[64][36];

    const int tid  = threadIdx.x;
    const int warp = tid >> 5;
    const int lane = tid & 31;
    const int g = lane >> 2;
    const int t = lane & 3;
    const int wrow = (warp & 3) * 32;
    const int wcol = (warp >> 2) * 32;
    const int m0 = blockIdx.x * 128;

    const unsigned as_base = (unsigned)__cvta_generic_to_shared(&As[0][0][0]);

    for (int i = tid; i < 64 * 36; i += 256) (&Wsm[0][0])[i] = 0u;
    __syncthreads();

    float acc[2][4][4];
#pragma unroll
    for (int mi = 0; mi < 2; mi++)
#pragma unroll
        for (int ni = 0; ni < 4; ni++)
#pragma unroll
            for (int r = 0; r < 4; r++) acc[mi][ni][r] = 0.f;

    const int wl_n  = tid & 63;
    const int wl_k0 = (tid >> 6) * 8;

    auto issue_A = [&](int buf, int k0) {
#pragma unroll
        for (int j = 0; j < 4; j++) {
            int i   = tid + j * 256;
            int row = i >> 3;
            int c4  = (i & 7) * 4;
            int sc  = c4 ^ (4 * (row & 7));
            unsigned dst = as_base + ((buf * 128 + row) * 32 + sc) * 4;
            cp_async16(dst, &A[(size_t)(m0 + row) * HW + k0 + c4]);
        }
        cp_commit();
    };

    issue_A(0, kbase);
    if (wl_n < PROJ) {
#pragma unroll
        for (int j = 0; j < 8; j++)
            Wsm[wl_n][wl_k0 + j] = f2tf32(W[(kbase + wl_k0 + j) * PROJ + wl_n]);
    }
    cp_wait0();
    __syncthreads();

    const int NT = KSLICE / 32;   // 32 tiles
    for (int kt = 0; kt < NT; kt++) {
        const int buf = kt & 1;
        const bool haveNext = (kt + 1 < NT);
        float wreg[8];
        if (haveNext) {
            const int k0n = kbase + (kt + 1) * 32;
            issue_A(buf ^ 1, k0n);
            if (wl_n < PROJ) {
#pragma unroll
                for (int j = 0; j < 8; j++)
                    wreg[j] = W[(k0n + wl_k0 + j) * PROJ + wl_n];
            }
        }

#pragma unroll
        for (int ks = 0; ks < 4; ks++) {
            const int kb = ks * 8;
            unsigned a[2][4];
#pragma unroll
            for (int mi = 0; mi < 2; mi++) {
                int n = wcol + mi * 16 + g;
                a[mi][0] = Wsm[n][kb + t];
                a[mi][1] = Wsm[n + 8][kb + t];
                a[mi][2] = Wsm[n][kb + t + 4];
                a[mi][3] = Wsm[n + 8][kb + t + 4];
            }
#pragma unroll
            for (int ni = 0; ni < 4; ni++) {
                int row = wrow + ni * 8 + g;
                unsigned b0 = As[buf][row][(kb + t) ^ (4 * (row & 7))];
                unsigned b1 = As[buf][row][(kb + t + 4) ^ (4 * (row & 7))];
                mma_tf32(acc[0][ni], a[0][0], a[0][1], a[0][2], a[0][3], b0, b1);
                mma_tf32(acc[1][ni], a[1][0], a[1][1], a[1][2], a[1][3], b0, b1);
            }
        }

        if (haveNext) {
            cp_wait0();
            __syncthreads();
            if (wl_n < PROJ) {
#pragma unroll
                for (int j = 0; j < 8; j++)
                    Wsm[wl_n][wl_k0 + j] = f2tf32(wreg[j]);
            }
            __syncthreads();
        }
    }

#pragma unroll
    for (int mi = 0; mi < 2; mi++) {
#pragma unroll
        for (int ni = 0; ni < 4; ni++) {
            int col0 = wcol + mi * 16 + g;
            int col2 = col0 + 8;
            int prow = m0 + wrow + ni * 8 + 2 * t;
            if (col0 < PROJ) {
                P[prow * PROJ + col0]       = acc[mi][ni][0];
                P[(prow + 1) * PROJ + col0] = acc[mi][ni][1];
            }
            if (col2 < PROJ) {
                P[prow * PROJ + col2]       = acc[mi][ni][2];
                P[(prow + 1) * PROJ + col2] = acc[mi][ni][3];
            }
        }
    }
}

// ---------------------------------------------------------------------------
// K1b: reduce split-K partials (4-way).
// ---------------------------------------------------------------------------
__global__ __launch_bounds__(256) void k_reduceP()
{
    const int i = blockIdx.x * 256 + threadIdx.x;
    const int per_z = (M_ROWS * PROJ) / 4;
    const int z = i / per_z;
    const int r = i - z * per_z;
    const float4* __restrict__ p = (const float4*)g_Pp;
    float4 a = p[(size_t)(z * KSPLIT + 0) * per_z + r];
    float4 b = p[(size_t)(z * KSPLIT + 1) * per_z + r];
    float4 c = p[(size_t)(z * KSPLIT + 2) * per_z + r];
    float4 d = p[(size_t)(z * KSPLIT + 3) * per_z + r];
    float4 o;
    o.x = (a.x + b.x) + (c.x + d.x);
    o.y = (a.y + b.y) + (c.y + d.y);
    o.z = (a.z + b.z) + (c.z + d.z);
    o.w = (a.w + b.w) + (c.w + d.w);
    ((float4*)g_P)[i] = o;
}

// ---------------------------------------------------------------------------
// K1c: pack wfc into mma-A fragment order (once; 917 KB, L2-resident).
// ---------------------------------------------------------------------------
__global__ __launch_bounds__(256) void k_packW(const float* __restrict__ wfc)
{
    const int idx = blockIdx.x * 256 + threadIdx.x;   // 0 .. 229375
    const int kk = idx >> 12;
    const int n  = idx & 4095;
    float val = (kk < PROJ) ? wfc[kk * HW + n] : 0.f;
    const int nblk = n >> 6, n6 = n & 63;
    const int N16 = n6 >> 4, hi = (n6 >> 3) & 1, gg = n6 & 7;
    const int K8 = kk >> 3, tt = kk & 3, hf = (kk >> 2) & 1;
    ((unsigned*)g_Wp)[(((nblk * 4 + N16) * 7 + K8) * 32 + gg * 4 + tt) * 4
                      + hi + 2 * hf] = f2tf32(val);
}

// ---------------------------------------------------------------------------
// K2a: Gram partials. grid (32 b, 8 cslice); 256 thr = 32 channels x 8 workers.
// ---------------------------------------------------------------------------
__global__ __launch_bounds__(256) void k_gram()
{
    const int b  = blockIdx.x;
    const int cs = blockIdx.y;
    const int tid = threadIdx.x;
    const int cl = tid >> 3;          // 0..31 channel-local
    const int w  = tid & 7;           // worker
    const int row = b * C_DIM + cs * 32 + cl;

    const float* __restrict__ pq = &g_P[0][row * PROJ];
    const float* __restrict__ pk = &g_P[1][row * PROJ];

    float qv[NH][2], kv[NH][2];
    const bool has2 = (w + 8 < LD);
#pragma unroll
    for (int i = 0; i < NH; i++) {
        qv[i][0] = __ldg(&pq[i * LD + w]);
        kv[i][0] = __ldg(&pk[i * LD + w]);
        qv[i][1] = has2 ? __ldg(&pq[i * LD + w + 8]) : 0.f;
        kv[i][1] = has2 ? __ldg(&pk[i * LD + w + 8]) : 0.f;
    }

    __shared__ float sG[32][26];

#pragma unroll
    for (int i = 0; i < NH; i++) {
#pragma unroll
        for (int j = 0; j < NH; j++) {
            float s = qv[i][0] * kv[j][0] + qv[i][1] * kv[j][1];
            s += __shfl_xor_sync(0xffffffffu, s, 1);
            s += __shfl_xor_sync(0xffffffffu, s, 2);
            s += __shfl_xor_sync(0xffffffffu, s, 4);
            if (w == 0) sG[cl][i * NH + j] = s;
        }
    }
    __syncthreads();

    if (tid < NH * NH) {  // reduce 32 channels, fixed order
        float a = 0.f;
#pragma unroll
        for (int cc = 0; cc < 32; cc++) a += sG[cc][tid];
        g_gramp[b][cs][tid] = a;
    }
}

// ---------------------------------------------------------------------------
// K2b: softmax. 1 block, 32 threads (one per batch).
// ---------------------------------------------------------------------------
__global__ __launch_bounds__(32) void k_soft()
{
    const int b = threadIdx.x;
    const float inv_scale = rsqrtf((float)(C_DIM * LD));
    float s[NH * NH];
#pragma unroll
    for (int tt = 0; tt < NH * NH; tt++) {
        float a = 0.f;
#pragma unroll
        for (int cs = 0; cs < 8; cs++) a += g_gramp[b][cs][tt];
        s[tt] = a * inv_scale;
    }
#pragma unroll
    for (int i = 0; i < NH; i++) {
        float mx = -1e30f;
#pragma unroll
        for (int j = 0; j < NH; j++) mx = fmaxf(mx, s[i * NH + j]);
        float sum = 0.f;
#pragma unroll
        for (int j = 0; j < NH; j++) {
            s[i * NH + j] = expf(s[i * NH + j] - mx);
            sum += s[i * NH + j];
        }
        float inv = 1.f / sum;
#pragma unroll
        for (int j = 0; j < NH; j++) g_attn[b][i * NH + j] = s[i * NH + j] * inv;
    }
}

// ---------------------------------------------------------------------------
// K2c: Va = Pv + attn @ Pv (per channel), written in packed mma-B frag order.
// ---------------------------------------------------------------------------
__global__ __launch_bounds__(256) void k_vawrite()
{
    const int b = blockIdx.x;
    const int c = threadIdx.x;
    const int row = b * C_DIM + c;
    const float* __restrict__ pv = &g_P[2][row * PROJ];

    __shared__ float sA[NH * NH];
    if (c < NH * NH) sA[c] = g_attn[b][c];
    __syncthreads();

    const int R8i = row >> 3, gg = row & 7;
    unsigned* __restrict__ vp = (unsigned*)g_Vp;
#pragma unroll
    for (int n = 0; n < NH; n++)
#pragma unroll
        for (int l = 0; l < LD; l++) {
            float a = pv[n * LD + l];
#pragma unroll
            for (int j = 0; j < NH; j++)
                a = fmaf(sA[n * NH + j], pv[j * LD + l], a);
            const int kk = n * LD + l;
            const int K8 = kk >> 3, tt = kk & 3, hf = (kk >> 2) & 1;
            vp[((R8i * 7 + K8) * 32 + gg * 4 + tt) * 2 + hf] = f2tf32(a);
        }
#pragma unroll
    for (int kk = PROJ; kk < 56; kk++) {
        const int K8 = kk >> 3, tt = kk & 3, hf = (kk >> 2) & 1;
        vp[((R8i * 7 + K8) * 32 + gg * 4 + tt) * 2 + hf] = 0u;
    }
}

// ---------------------------------------------------------------------------
// K3: output GEMM + residual + fused BN partial stats (R12 version).
// Fragments straight from packed globals; staged float4 epilogue.
// ---------------------------------------------------------------------------
__global__ __launch_bounds__(256) void k_out_tc(
    const float* __restrict__ v, float* __restrict__ out)
{
    __shared__ float Acc[128][68];

    const int tid  = threadIdx.x;
    const int warp = tid >> 5;
    const int lane = tid & 31;
    const int g = lane >> 2;
    const int t = lane & 3;
    const int wrow = (warp & 3) * 32;
    const int wcol = (warp >> 2) * 32;
    const int n0 = blockIdx.x * 64;
    const int m0 = blockIdx.y * 128;

    const uint4* __restrict__ Wp =
        g_Wp + (size_t)(blockIdx.x * 4 + (warp >> 2) * 2) * 7 * 32;
    const uint2* __restrict__ Vp =
        g_Vp + (size_t)((m0 >> 3) + (warp & 3) * 4) * 7 * 32;

    float acc[2][4][4];
#pragma unroll
    for (int mi = 0; mi < 2; mi++)
#pragma unroll
        for (int ni = 0; ni < 4; ni++)
#pragma unroll
            for (int r = 0; r < 4; r++) acc[mi][ni][r] = 0.f;

#pragma unroll
    for (int ks = 0; ks < 7; ks++) {
        uint4 av0 = __ldg(&Wp[ks * 32 + lane]);
        uint4 av1 = __ldg(&Wp[(7 + ks) * 32 + lane]);
#pragma unroll
        for (int ni = 0; ni < 4; ni++) {
            uint2 bv = __ldg(&Vp[(ni * 7 + ks) * 32 + lane]);
            mma_tf32(acc[0][ni], av0.x, av0.y, av0.z, av0.w, bv.x, bv.y);
            mma_tf32(acc[1][ni], av1.x, av1.y, av1.z, av1.w, bv.x, bv.y);
        }
    }

#pragma unroll
    for (int mi = 0; mi < 2; mi++) {
#pragma unroll
        for (int ni = 0; ni < 4; ni++) {
            int row = wrow + ni * 8 + 2 * t;
            int col = wcol + mi * 16 + g;
            Acc[row][col]         = acc[mi][ni][0];
            Acc[row + 1][col]     = acc[mi][ni][1];
            Acc[row][col + 8]     = acc[mi][ni][2];
            Acc[row + 1][col + 8] = acc[mi][ni][3];
        }
    }
    __syncthreads();

#pragma unroll
    for (int it = 0; it < 8; it++) {
        int f   = tid + it * 256;
        int row = f >> 4;
        int c4  = (f & 15) * 4;
        float4 a = *(float4*)&Acc[row][c4];
        size_t gi = (size_t)(m0 + row) * HW + n0 + c4;
        float4 vv = *(const float4*)&v[gi];
        float4 o;
        o.x = vv.x + a.x;
        o.y = vv.y + a.y;
        o.z = vv.z + a.z;
        o.w = vv.w + a.w;
        *(float4*)&out[gi] = o;
        float s  = (o.x + o.y) + (o.z + o.w);
        float qq = (o.x * o.x + o.y * o.y) + (o.z * o.z + o.w * o.w);
#pragma unroll
        for (int msk = 1; msk <= 8; msk <<= 1) {
            s  += __shfl_xor_sync(0xffffffffu, s, msk);
            qq += __shfl_xor_sync(0xffffffffu, qq, msk);
        }
        if ((lane & 15) == 0) {
            g_osum[blockIdx.x][m0 + row] = s;
            g_osq[blockIdx.x][m0 + row]  = qq;
        }
    }
}

// ---------------------------------------------------------------------------
// K4: combine partials -> per-channel scale/shift.
// ---------------------------------------------------------------------------
__global__ __launch_bounds__(256) void k_bnfinal(
    const float* __restrict__ gamma, const float* __restrict__ beta)
{
    const int c = blockIdx.x;
    const int tid = threadIdx.x;
    float s = 0.f, s2 = 0.f;
    for (int i = tid; i < B_DIM * 64; i += 256) {
        int b  = i >> 6;
        int nb = i & 63;
        int row = b * C_DIM + c;
        s  += g_osum[nb][row];
        s2 += g_osq[nb][row];
    }
    __shared__ float rs[256], rs2[256];
    rs[tid] = s; rs2[tid] = s2;
    __syncthreads();
    for (int off = 128; off > 0; off >>= 1) {
        if (tid < off) { rs[tid] += rs[tid + off]; rs2[tid] += rs2[tid + off]; }
        __syncthreads();
    }
    if (tid == 0) {
        const float inv_n = 1.f / (float)(B_DIM * HW);
        float mean = rs[0] * inv_n;
        float var  = rs2[0] * inv_n - mean * mean;
        float sc = gamma[c] * rsqrtf(var + BN_EPS);
        g_scale[c] = sc;
        g_shift[c] = beta[c] - mean * sc;
    }
}

// ---------------------------------------------------------------------------
// K5: apply BN affine in place (streaming).
// ---------------------------------------------------------------------------
__global__ __launch_bounds__(256) void k_apply(float* __restrict__ out)
{
    float4* __restrict__ p = (float4*)out;
    const int idx = blockIdx.x * 256 + threadIdx.x;
#pragma unroll
    for (int tt = 0; tt < 4; tt++) {
        int i = idx + tt * (8192 * 256);
        int c = (i >> 10) & 255;
        float sc = g_scale[c], sh = g_shift[c];
        float4 x = p[i];
        x.x = fmaf(x.x, sc, sh);
        x.y = fmaf(x.y, sc, sh);
        x.z = fmaf(x.z, sc, sh);
        x.w = fmaf(x.w, sc, sh);
        p[i] = x;
    }
}

// ---------------------------------------------------------------------------
extern "C" void kernel_launch(void* const* d_in, const int* in_sizes, int n_in,
                              void* d_out, int out_size)
{
    (void)in_sizes; (void)n_in; (void)out_size;
    const float* q     = (const float*)d_in[0];
    const float* k     = (const float*)d_in[1];
    const float* v     = (const float*)d_in[2];
    const float* wq    = (const float*)d_in[3];
    const float* wk    = (const float*)d_in[4];
    const float* wv    = (const float*)d_in[5];
    const float* wfc   = (const float*)d_in[6];
    const float* gamma = (const float*)d_in[7];
    const float* beta  = (const float*)d_in[8];
    float* out = (float*)d_out;

    k_proj_tc<<<dim3(M_ROWS / 128, KSPLIT, 3), 256>>>(q, k, v, wq, wk, wv);
    k_packW<<<(4096 * 56) / 256, 256>>>(wfc);
    k_reduceP<<<(3 * M_ROWS * PROJ / 4) / 256, 256>>>();
    k_gram<<<dim3(B_DIM, 8), 256>>>();
    k_soft<<<1, 32>>>();
    k_vawrite<<<B_DIM, 256>>>();
    k_out_tc<<<dim3(HW / 64, M_ROWS / 128), 256>>>(v, out);
    k_bnfinal<<<C_DIM, 256>>>(gamma, beta);
    k_apply<<<8192, 256>>>(out);
}